// round 3
// baseline (speedup 1.0000x reference)
#include <cuda_runtime.h>
#include <cstdint>
#include <math_constants.h>

// Problem constants (fixed by the dataset)
#define N_PTS   98304      // B*H*W = 96*32*32
#define C_DIM   256
#define HW      1024       // 32*32
#define NSAMP   491
#define NITER   490        // NSAMP - 1
#define NBLK    96         // persistent blocks, all co-resident
#define NTHR    1024       // threads per block; each thread owns 1 point

// Scratch (device globals: no allocation allowed)
__device__ float g_featT[(size_t)C_DIM * N_PTS];          // [C][N], ~100.6 MB
__device__ unsigned long long g_bmax[2][NBLK];            // double-buffered block maxima
__device__ int g_sel[NSAMP];                              // selected indices
__device__ volatile unsigned g_bar;                       // grid barrier counter

// ---------------------------------------------------------------------------
// Init: reset barrier, transpose [B,C,H,W] -> featT[c*N + b*HW + hw]
// ---------------------------------------------------------------------------
__global__ void k_init(const float* __restrict__ in) {
    if (blockIdx.x == 0 && threadIdx.x == 0) { g_bar = 0; g_sel[0] = 0; }
    const int blk = blockIdx.x;          // == b*256 + c (input is [b][c][hw])
    const int b = blk >> 8;
    const int c = blk & 255;
    const float4* src = reinterpret_cast<const float4*>(in + (size_t)blk * HW);
    float4* dst = reinterpret_cast<float4*>(g_featT + (size_t)c * N_PTS + (size_t)b * HW);
    dst[threadIdx.x] = src[threadIdx.x];
}

// ---------------------------------------------------------------------------
// Bit-exact XLA row-reduce, evaluated DEPTH-FIRST to avoid register spill.
// Leaf l: p[l] = sum_{j=0..7} (x[j*32+l] - q[j*32+l])^2, sequential in j.
// Tree: a[l]=p[l]+p[l+16]; b=a[l]+a[l+8]; c=b[l]+b[l+4]; d=c[l]+c[l+2]; e=d0+d1.
// Depth-first evaluation reorders only INDEPENDENT adds -> bit-identical result,
// but keeps <= ~6 partials live instead of 32 accumulators.
// ---------------------------------------------------------------------------
template<int L>
__device__ __forceinline__ float leafT(const float* __restrict__ base,
                                       const float* __restrict__ q) {
    float acc = 0.f;
    #pragma unroll
    for (int j = 0; j < 8; ++j) {
        float v = base[(size_t)(j * 32 + L) * N_PTS];
        float d = __fsub_rn(v, q[j * 32 + L]);
        acc = __fadd_rn(acc, __fmul_rn(d, d));      // no FMA contraction
    }
    return acc;
}
template<int L>
__device__ __forceinline__ float nA(const float* __restrict__ b, const float* __restrict__ q) {
    return __fadd_rn(leafT<L>(b, q), leafT<L + 16>(b, q));
}
template<int L>
__device__ __forceinline__ float nB(const float* __restrict__ b, const float* __restrict__ q) {
    return __fadd_rn(nA<L>(b, q), nA<L + 8>(b, q));
}
template<int L>
__device__ __forceinline__ float nC(const float* __restrict__ b, const float* __restrict__ q) {
    return __fadd_rn(nB<L>(b, q), nB<L + 4>(b, q));
}
template<int L>
__device__ __forceinline__ float nD(const float* __restrict__ b, const float* __restrict__ q) {
    return __fadd_rn(nC<L>(b, q), nC<L + 2>(b, q));
}
__device__ __forceinline__ float dist2_xla(const float* __restrict__ b,
                                           const float* __restrict__ q) {
    return __fadd_rn(nD<0>(b, q), nD<1>(b, q));
}

// ---------------------------------------------------------------------------
// Persistent farthest-point-sampling kernel.
// 96 blocks x 1024 threads; thread t of block B owns point n = B*1024 + t.
// min_d stays in a register across all 490 iterations.
// ---------------------------------------------------------------------------
__global__ void __launch_bounds__(NTHR, 1) k_fps() {
    __shared__ float sq[C_DIM];                 // query vector broadcast
    __shared__ unsigned long long swarp[NTHR / 32];
    __shared__ int s_q;

    const int tid  = threadIdx.x;
    const int lane = tid & 31;
    const int wid  = tid >> 5;
    const int n    = blockIdx.x * NTHR + tid;
    const float* __restrict__ base = g_featT + n;

    float mind = CUDART_INF_F;

    // initial query: index 0
    if (tid < C_DIM) sq[tid] = g_featT[(size_t)tid * N_PTS];
    __syncthreads();

    for (int it = 0; it < NITER; ++it) {
        // ---- squared distance, XLA order, depth-first tree ----
        float s2 = dist2_xla(base, sq);
        mind = fminf(mind, __fsqrt_rn(s2));

        // ---- argmax, first-index-wins: key = bits(min_d)<<32 | ~idx ----
        unsigned long long best =
            ((unsigned long long)__float_as_uint(mind) << 32) | (unsigned)~n;
        #pragma unroll
        for (int off = 16; off; off >>= 1) {
            unsigned long long o = __shfl_xor_sync(0xffffffffu, best, off);
            if (o > best) best = o;
        }
        if (lane == 0) swarp[wid] = best;
        __syncthreads();

        if (wid == 0) {
            unsigned long long b = swarp[lane];            // 32 warps -> 32 entries
            #pragma unroll
            for (int off = 16; off; off >>= 1) {
                unsigned long long o = __shfl_xor_sync(0xffffffffu, b, off);
                if (o > b) b = o;
            }
            if (lane == 0) {
                // publish block max (double-buffered by iteration parity)
                *(volatile unsigned long long*)&g_bmax[it & 1][blockIdx.x] = b;
                __threadfence();                           // release
                atomicAdd((unsigned*)&g_bar, 1u);
                const unsigned target = (unsigned)NBLK * (unsigned)(it + 1);
                while (g_bar < target) { }                 // grid barrier spin
                __threadfence();                           // acquire
            }
        }
        __syncthreads();

        // ---- every block redundantly reduces the 96 block maxima ----
        if (wid == 0) {
            unsigned long long b = 0;
            for (int j = lane; j < NBLK; j += 32) {
                unsigned long long o = *(volatile unsigned long long*)&g_bmax[it & 1][j];
                if (o > b) b = o;
            }
            #pragma unroll
            for (int off = 16; off; off >>= 1) {
                unsigned long long o = __shfl_xor_sync(0xffffffffu, b, off);
                if (o > b) b = o;
            }
            if (lane == 0) {
                const int q = (int)~(unsigned)b;
                s_q = q;
                if (blockIdx.x == 0) g_sel[it + 1] = q;
            }
        }
        __syncthreads();

        // ---- load next query vector into shared ----
        const int q = s_q;
        if (tid < C_DIM) sq[tid] = g_featT[(size_t)tid * N_PTS + q];
        __syncthreads();
    }
}

// ---------------------------------------------------------------------------
// Gather: out = [sampled feats (491*256) | sampled weights (491) | indices (491)]
// ---------------------------------------------------------------------------
__global__ void k_gather(const float* __restrict__ w, float* __restrict__ out) {
    const int s = blockIdx.x;           // 0..490
    const int idx = g_sel[s];
    out[s * C_DIM + threadIdx.x] = g_featT[(size_t)threadIdx.x * N_PTS + idx];
    if (threadIdx.x == 0) {
        out[NSAMP * C_DIM + s]         = w[idx];
        out[NSAMP * C_DIM + NSAMP + s] = (float)idx;
    }
}

// ---------------------------------------------------------------------------
extern "C" void kernel_launch(void* const* d_in, const int* in_sizes, int n_in,
                              void* d_out, int out_size) {
    const float* features = (const float*)d_in[0];   // [96,256,32,32] f32
    const float* weights  = (const float*)d_in[1];   // [98304] f32
    (void)in_sizes; (void)n_in; (void)out_size;      // num_samples fixed at 491

    k_init<<<(96 * 256), 256>>>(features);
    k_fps<<<NBLK, NTHR>>>();
    k_gather<<<NSAMP, C_DIM>>>(weights, (float*)d_out);
}

// round 4
// speedup vs baseline: 2.9109x; 2.9109x over previous
#include <cuda_runtime.h>
#include <cstdint>
#include <math_constants.h>

// Problem constants (fixed by the dataset)
#define N_PTS   98304      // B*H*W = 96*32*32
#define C_DIM   256
#define HW      1024       // 32*32
#define NSAMP   491
#define NITER   490        // NSAMP - 1
#define NBLK    96         // persistent blocks, all co-resident
#define NTHR    1024       // 32 warps per block; each warp owns 32 points

// Scratch (device globals: no allocation allowed)
__device__ float g_feat[(size_t)N_PTS * C_DIM];           // [N][C] row-major, ~100.6 MB
__device__ unsigned long long g_bmax[2][NBLK];            // double-buffered block maxima
__device__ int g_sel[NSAMP];                              // selected indices
__device__ volatile unsigned g_bar;                       // grid barrier counter

// ---------------------------------------------------------------------------
// Init: reset barrier + tiled transpose [B,C,HW] -> g_feat[(b*HW+hw)*C + c]
// grid = 96*256 blocks of 256 threads; each block moves a 32x32 tile.
// blockIdx.x = b*256 + ct*32 + ht  (ct: c-tile 0..7, ht: hw-tile 0..31)
// ---------------------------------------------------------------------------
__global__ void k_init(const float* __restrict__ in) {
    if (blockIdx.x == 0 && threadIdx.x == 0) { g_bar = 0; g_sel[0] = 0; }
    __shared__ float tile[32][33];
    const int b  = blockIdx.x >> 8;
    const int t  = blockIdx.x & 255;
    const int ct = t >> 5;            // 0..7   (c-tile)
    const int ht = t & 31;            // 0..31  (hw-tile)
    const int tx = threadIdx.x & 31;
    const int ty = threadIdx.x >> 5;  // 0..7

    const float* src = in + ((size_t)b * C_DIM + ct * 32) * HW + ht * 32;
    #pragma unroll
    for (int r = 0; r < 4; ++r)
        tile[ty + r * 8][tx] = src[(size_t)(ty + r * 8) * HW + tx];
    __syncthreads();

    float* dst = g_feat + ((size_t)b * HW + ht * 32) * C_DIM + ct * 32;
    #pragma unroll
    for (int r = 0; r < 4; ++r)
        dst[(size_t)(ty + r * 8) * C_DIM + tx] = tile[tx][ty + r * 8];
}

// ---------------------------------------------------------------------------
// Persistent FPS. One warp per point-group of 32; the warp reduction
// reproduces the XLA row-reduce bit pattern NATIVELY:
//   lane l accumulates cols {l, l+32, ..., l+224} sequentially (no FMA),
//   then shfl_down tree (16,8,4,2,1); lane 0 holds the exact sum.
// ---------------------------------------------------------------------------
__global__ void __launch_bounds__(NTHR, 1) k_fps() {
    __shared__ float sq[C_DIM];                 // query vector broadcast
    __shared__ unsigned long long swarp[NTHR / 32];
    __shared__ int s_q;

    const int tid  = threadIdx.x;
    const int lane = tid & 31;
    const int wid  = tid >> 5;
    const int n0   = blockIdx.x * NTHR + wid * 32;   // warp's first point
    const float* __restrict__ wbase = g_feat + (size_t)n0 * C_DIM;

    float mind = CUDART_INF_F;                  // min_d of point n0+lane

    // initial query: row 0
    if (tid < C_DIM) sq[tid] = g_feat[tid];
    __syncthreads();

    for (int it = 0; it < NITER; ++it) {
        // hoist query values this lane needs (cols lane, lane+32, ..., lane+224)
        float qv[8];
        #pragma unroll
        for (int j = 0; j < 8; ++j) qv[j] = sq[j * 32 + lane];

        // ---- 32 points, 2 at a time (16 independent loads in flight) ----
        #pragma unroll
        for (int i = 0; i < 32; i += 2) {
            const float* r0 = wbase + (size_t)i * C_DIM;
            const float* r1 = r0 + C_DIM;
            float a0 = 0.f, a1 = 0.f;
            #pragma unroll
            for (int j = 0; j < 8; ++j) {
                float v0 = r0[j * 32 + lane];
                float v1 = r1[j * 32 + lane];
                float d0 = __fsub_rn(v0, qv[j]);
                float d1 = __fsub_rn(v1, qv[j]);
                a0 = __fadd_rn(a0, __fmul_rn(d0, d0));   // no contraction
                a1 = __fadd_rn(a1, __fmul_rn(d1, d1));
            }
            #pragma unroll
            for (int off = 16; off; off >>= 1) {
                a0 = __fadd_rn(a0, __shfl_down_sync(0xffffffffu, a0, off));
                a1 = __fadd_rn(a1, __shfl_down_sync(0xffffffffu, a1, off));
            }
            float s0 = __shfl_sync(0xffffffffu, a0, 0);
            float s1 = __shfl_sync(0xffffffffu, a1, 0);
            if (lane == i)     mind = fminf(mind, __fsqrt_rn(s0));
            if (lane == i + 1) mind = fminf(mind, __fsqrt_rn(s1));
        }

        // ---- argmax, first-index-wins: key = bits(min_d)<<32 | ~idx ----
        unsigned long long best =
            ((unsigned long long)__float_as_uint(mind) << 32) | (unsigned)~(n0 + lane);
        #pragma unroll
        for (int off = 16; off; off >>= 1) {
            unsigned long long o = __shfl_xor_sync(0xffffffffu, best, off);
            if (o > best) best = o;
        }
        if (lane == 0) swarp[wid] = best;
        __syncthreads();

        if (wid == 0) {
            unsigned long long b = swarp[lane];            // 32 warps -> 32 entries
            #pragma unroll
            for (int off = 16; off; off >>= 1) {
                unsigned long long o = __shfl_xor_sync(0xffffffffu, b, off);
                if (o > b) b = o;
            }
            if (lane == 0) {
                *(volatile unsigned long long*)&g_bmax[it & 1][blockIdx.x] = b;
                __threadfence();                           // release
                atomicAdd((unsigned*)&g_bar, 1u);
                const unsigned target = (unsigned)NBLK * (unsigned)(it + 1);
                while (g_bar < target) { }                 // grid barrier spin
                __threadfence();                           // acquire
            }
        }
        __syncthreads();

        // ---- every block redundantly reduces the 96 block maxima ----
        if (wid == 0) {
            unsigned long long b = 0;
            for (int j = lane; j < NBLK; j += 32) {
                unsigned long long o = *(volatile unsigned long long*)&g_bmax[it & 1][j];
                if (o > b) b = o;
            }
            #pragma unroll
            for (int off = 16; off; off >>= 1) {
                unsigned long long o = __shfl_xor_sync(0xffffffffu, b, off);
                if (o > b) b = o;
            }
            if (lane == 0) {
                const int q = (int)~(unsigned)b;
                s_q = q;
                if (blockIdx.x == 0) g_sel[it + 1] = q;
            }
        }
        __syncthreads();

        // ---- load next query row (contiguous) into shared ----
        const int q = s_q;
        if (tid < C_DIM) sq[tid] = g_feat[(size_t)q * C_DIM + tid];
        __syncthreads();
    }
}

// ---------------------------------------------------------------------------
// Gather: out = [sampled feats (491*256) | sampled weights (491) | indices (491)]
// Row-major copy is fully coalesced now.
// ---------------------------------------------------------------------------
__global__ void k_gather(const float* __restrict__ w, float* __restrict__ out) {
    const int s = blockIdx.x;           // 0..490
    const int idx = g_sel[s];
    out[s * C_DIM + threadIdx.x] = g_feat[(size_t)idx * C_DIM + threadIdx.x];
    if (threadIdx.x == 0) {
        out[NSAMP * C_DIM + s]         = w[idx];
        out[NSAMP * C_DIM + NSAMP + s] = (float)idx;
    }
}

// ---------------------------------------------------------------------------
extern "C" void kernel_launch(void* const* d_in, const int* in_sizes, int n_in,
                              void* d_out, int out_size) {
    const float* features = (const float*)d_in[0];   // [96,256,32,32] f32
    const float* weights  = (const float*)d_in[1];   // [98304] f32
    (void)in_sizes; (void)n_in; (void)out_size;      // num_samples fixed at 491

    k_init<<<(96 * 256), 256>>>(features);
    k_fps<<<NBLK, NTHR>>>();
    k_gather<<<NSAMP, C_DIM>>>(weights, (float*)d_out);
}

// round 5
// speedup vs baseline: 4.5949x; 1.5785x over previous
#include <cuda_runtime.h>
#include <cuda_fp16.h>
#include <cstdint>
#include <math_constants.h>

// Problem constants (fixed by the dataset)
#define N_PTS   98304      // B*H*W = 96*32*32
#define C_DIM   256
#define HW      1024       // 32*32
#define NSAMP   491
#define NITER   490        // NSAMP - 1
#define NBLK    128        // persistent blocks, all co-resident
#define NTHR    768        // 24 warps/block; each warp owns 32 points

// Scratch (device globals: no allocation allowed)
__device__ float  g_feat[(size_t)N_PTS * C_DIM];  // [N][C] fp32 exact, ~100.6 MB
__device__ __half g_h[(size_t)N_PTS * C_DIM];     // [N][C] fp16 screen, ~50.3 MB
__device__ float  g_nv2[N_PTS];                   // sum v_h^2 per point
__device__ unsigned long long g_bmax[2][NBLK];    // double-buffered block maxima
__device__ int g_sel[NSAMP];                      // selected indices
__device__ volatile unsigned g_bar;               // grid barrier counter

// ---------------------------------------------------------------------------
// Init A: reset barrier + tiled transpose [B,C,HW] -> g_feat[(b*HW+hw)*C + c]
// ---------------------------------------------------------------------------
__global__ void k_init(const float* __restrict__ in) {
    if (blockIdx.x == 0 && threadIdx.x == 0) { g_bar = 0; g_sel[0] = 0; }
    __shared__ float tile[32][33];
    const int b  = blockIdx.x >> 8;
    const int t  = blockIdx.x & 255;
    const int ct = t >> 5;            // c-tile 0..7
    const int ht = t & 31;            // hw-tile 0..31
    const int tx = threadIdx.x & 31;
    const int ty = threadIdx.x >> 5;  // 0..7

    const float* src = in + ((size_t)b * C_DIM + ct * 32) * HW + ht * 32;
    #pragma unroll
    for (int r = 0; r < 4; ++r)
        tile[ty + r * 8][tx] = src[(size_t)(ty + r * 8) * HW + tx];
    __syncthreads();

    float* dst = g_feat + ((size_t)b * HW + ht * 32) * C_DIM + ct * 32;
    #pragma unroll
    for (int r = 0; r < 4; ++r)
        dst[(size_t)(ty + r * 8) * C_DIM + tx] = tile[tx][ty + r * 8];
}

// ---------------------------------------------------------------------------
// Init B: fp16 copy + nv2 = sum(v_h^2).  One warp per point.
// ---------------------------------------------------------------------------
__global__ void k_half() {
    const int p    = blockIdx.x * 8 + (threadIdx.x >> 5);
    const int lane = threadIdx.x & 31;
    const float* row = g_feat + (size_t)p * C_DIM;
    __half*      hrw = g_h    + (size_t)p * C_DIM;
    float acc = 0.f;
    #pragma unroll
    for (int j = 0; j < 8; ++j) {
        float v = row[j * 32 + lane];
        __half h = __float2half(v);            // round-to-nearest
        hrw[j * 32 + lane] = h;
        float vh = __half2float(h);            // exact
        acc = fmaf(vh, vh, acc);
    }
    #pragma unroll
    for (int off = 16; off; off >>= 1)
        acc += __shfl_xor_sync(0xffffffffu, acc, off);
    if (lane == 0) g_nv2[p] = acc;
}

// ---------------------------------------------------------------------------
// Persistent FPS with certified fp16 screen.
// Exact path (on screen failure) is the verified bit-exact XLA warp reduce:
//   lane l accumulates cols {l, l+32,...,l+224} sequentially (no FMA),
//   shfl_down tree (16,8,4,2,1), lane 0 holds the exact sum.
// ---------------------------------------------------------------------------
__global__ void __launch_bounds__(NTHR, 1) k_fps() {
    __shared__ float sq[C_DIM];                 // query vector (exact fp32)
    __shared__ unsigned long long swarp[NTHR / 32];
    __shared__ int s_q;

    const int tid  = threadIdx.x;
    const int lane = tid & 31;
    const int wid  = tid >> 5;                  // 0..23
    const int n0   = blockIdx.x * NTHR + wid * 32;
    const __half* __restrict__ hbase = g_h    + (size_t)n0 * C_DIM;
    const float*  __restrict__ fbase = g_feat + (size_t)n0 * C_DIM;
    const int mypoint = n0 + lane;

    float mind = CUDART_INF_F;

    // hoisted per-point screen constants
    const float mynv2 = g_nv2[mypoint];
    const float e2    = 4.78e-7f * mynv2 + 1e-12f;          // >= sum e_i^2
    const float se2   = sqrtf(e2) * 1.0000005f + 1e-6f;     // safe sqrt bound
    const float sqnv2 = sqrtf(mynv2) * 1.0000005f;

    if (tid < C_DIM) sq[tid] = g_feat[tid];     // initial query: row 0
    __syncthreads();

    for (int it = 0; it < NITER; ++it) {
        // per-lane q values for the screen dot (halves 4*lane..+3, 128+4*lane..+3)
        float qa0 = sq[4 * lane],       qa1 = sq[4 * lane + 1];
        float qa2 = sq[4 * lane + 2],   qa3 = sq[4 * lane + 3];
        float qb0 = sq[128 + 4 * lane], qb1 = sq[128 + 4 * lane + 1];
        float qb2 = sq[128 + 4 * lane + 2], qb3 = sq[128 + 4 * lane + 3];

        // nq2 (approximate; covered by margin padding)
        float nq2 = qa0*qa0 + qa1*qa1 + qa2*qa2 + qa3*qa3
                  + qb0*qb0 + qb1*qb1 + qb2*qb2 + qb3*qb3;
        #pragma unroll
        for (int off = 16; off; off >>= 1)
            nq2 += __shfl_xor_sync(0xffffffffu, nq2, off);
        const float sqnq2 = sqrtf(nq2) * 1.0000005f;

        // ---- screen: dot(v_h, q) for the warp's 32 points ----
        float mydot = 0.f;
        #pragma unroll
        for (int i = 0; i < 32; ++i) {
            const uint2* r = reinterpret_cast<const uint2*>(hbase + (size_t)i * C_DIM);
            uint2 u0 = r[lane];        // halves 4*lane .. 4*lane+3
            uint2 u1 = r[32 + lane];   // halves 128+4*lane .. +3
            float2 f0 = __half22float2(*reinterpret_cast<__half2*>(&u0.x));
            float2 f1 = __half22float2(*reinterpret_cast<__half2*>(&u0.y));
            float2 f2 = __half22float2(*reinterpret_cast<__half2*>(&u1.x));
            float2 f3 = __half22float2(*reinterpret_cast<__half2*>(&u1.y));
            float acc = f0.x * qa0;
            acc = fmaf(f0.y, qa1, acc);
            acc = fmaf(f1.x, qa2, acc);
            acc = fmaf(f1.y, qa3, acc);
            acc = fmaf(f2.x, qb0, acc);
            acc = fmaf(f2.y, qb1, acc);
            acc = fmaf(f3.x, qb2, acc);
            acc = fmaf(f3.y, qb3, acc);
            #pragma unroll
            for (int off = 16; off; off >>= 1)
                acc += __shfl_xor_sync(0xffffffffu, acc, off);
            mydot = (lane == i) ? acc : mydot;
        }

        // ---- certified lower bound on true distance of my point ----
        float sc = mynv2 + nq2 - 2.f * mydot;                       // approx sq dist
        float A  = 1.05f * (1.6e-5f * (mynv2 + nq2) + 3.3e-5f * sqnv2 * sqnq2) + 1e-3f;
        float lb = sqrtf(fmaxf(sc - A, 0.f)) * (1.f - 2e-7f) - se2;
        bool need = !(lb >= mind);                                   // NaN/inf-safe

        // ---- exact recheck (bit-exact XLA reduce) for flagged lanes ----
        unsigned mask = __ballot_sync(0xffffffffu, need);
        while (mask) {
            const int i = __ffs(mask) - 1;
            mask &= mask - 1;
            const float* row = fbase + (size_t)i * C_DIM;
            float a = 0.f;
            #pragma unroll
            for (int j = 0; j < 8; ++j) {
                float v = row[j * 32 + lane];
                float d = __fsub_rn(v, sq[j * 32 + lane]);
                a = __fadd_rn(a, __fmul_rn(d, d));     // no contraction
            }
            #pragma unroll
            for (int off = 16; off; off >>= 1)
                a = __fadd_rn(a, __shfl_down_sync(0xffffffffu, a, off));
            float s = __shfl_sync(0xffffffffu, a, 0);
            if (lane == i) mind = fminf(mind, __fsqrt_rn(s));
        }

        // ---- argmax, first-index-wins: key = bits(min_d)<<32 | ~idx ----
        unsigned long long best =
            ((unsigned long long)__float_as_uint(mind) << 32) | (unsigned)~mypoint;
        #pragma unroll
        for (int off = 16; off; off >>= 1) {
            unsigned long long o = __shfl_xor_sync(0xffffffffu, best, off);
            if (o > best) best = o;
        }
        if (lane == 0) swarp[wid] = best;
        __syncthreads();

        if (wid == 0) {
            unsigned long long b = (lane < NTHR / 32) ? swarp[lane] : 0ULL;
            #pragma unroll
            for (int off = 16; off; off >>= 1) {
                unsigned long long o = __shfl_xor_sync(0xffffffffu, b, off);
                if (o > b) b = o;
            }
            if (lane == 0) {
                *(volatile unsigned long long*)&g_bmax[it & 1][blockIdx.x] = b;
                __threadfence();                           // release
                atomicAdd((unsigned*)&g_bar, 1u);
                const unsigned target = (unsigned)NBLK * (unsigned)(it + 1);
                while (g_bar < target) { }                 // grid barrier spin
                __threadfence();                           // acquire
            }
        }
        __syncthreads();

        // ---- every block redundantly reduces the 128 block maxima ----
        if (wid == 0) {
            unsigned long long b = 0;
            #pragma unroll
            for (int j = 0; j < NBLK / 32; ++j) {
                unsigned long long o =
                    *(volatile unsigned long long*)&g_bmax[it & 1][j * 32 + lane];
                if (o > b) b = o;
            }
            #pragma unroll
            for (int off = 16; off; off >>= 1) {
                unsigned long long o = __shfl_xor_sync(0xffffffffu, b, off);
                if (o > b) b = o;
            }
            if (lane == 0) {
                const int q = (int)~(unsigned)b;
                s_q = q;
                if (blockIdx.x == 0) g_sel[it + 1] = q;
            }
        }
        __syncthreads();

        // ---- load next query row (contiguous fp32) into shared ----
        const int q = s_q;
        if (tid < C_DIM) sq[tid] = g_feat[(size_t)q * C_DIM + tid];
        __syncthreads();
    }
}

// ---------------------------------------------------------------------------
// Gather: out = [sampled feats (491*256) | sampled weights (491) | indices (491)]
// ---------------------------------------------------------------------------
__global__ void k_gather(const float* __restrict__ w, float* __restrict__ out) {
    const int s = blockIdx.x;           // 0..490
    const int idx = g_sel[s];
    out[s * C_DIM + threadIdx.x] = g_feat[(size_t)idx * C_DIM + threadIdx.x];
    if (threadIdx.x == 0) {
        out[NSAMP * C_DIM + s]         = w[idx];
        out[NSAMP * C_DIM + NSAMP + s] = (float)idx;
    }
}

// ---------------------------------------------------------------------------
extern "C" void kernel_launch(void* const* d_in, const int* in_sizes, int n_in,
                              void* d_out, int out_size) {
    const float* features = (const float*)d_in[0];   // [96,256,32,32] f32
    const float* weights  = (const float*)d_in[1];   // [98304] f32
    (void)in_sizes; (void)n_in; (void)out_size;      // num_samples fixed at 491

    k_init<<<(96 * 256), 256>>>(features);
    k_half<<<N_PTS / 8, 256>>>();
    k_fps<<<NBLK, NTHR>>>();
    k_gather<<<NSAMP, C_DIM>>>(weights, (float*)d_out);
}

// round 6
// speedup vs baseline: 8.7488x; 1.9040x over previous
#include <cuda_runtime.h>
#include <cstdint>
#include <math_constants.h>

// Problem constants (fixed by the dataset)
#define N_PTS   98304      // B*H*W = 96*32*32
#define C_DIM   256
#define HW      1024       // 32*32
#define NSAMP   491
#define NITER   490        // NSAMP - 1
#define NBLK    128        // persistent blocks (98304/768)
#define NTHR    768        // 24 warps/block; each warp owns 32 points

// Scratch (device globals: no allocation allowed)
__device__ float g_feat[(size_t)N_PTS * C_DIM];   // [N][C] fp32 exact, ~100.6 MB
__device__ uint2 g_q8[(size_t)N_PTS * 32];        // [N][32] packed int8 rows, 25.2 MB
__device__ float g_sv[N_PTS];                     // per-point int8 scale
__device__ float g_nvh2[N_PTS];                   // sv^2 * sum(v8^2)
__device__ float g_env[N_PTS];                    // certified ||v - sv*v8|| upper bound
__device__ unsigned long long g_bmax[2][NBLK];    // double-buffered block maxima
__device__ int g_sel[NSAMP];                      // selected indices
__device__ volatile unsigned g_bar;               // grid barrier counter

// ---------------------------------------------------------------------------
// Init A: reset barrier + tiled transpose [B,C,HW] -> g_feat[(b*HW+hw)*C + c]
// ---------------------------------------------------------------------------
__global__ void k_init(const float* __restrict__ in) {
    if (blockIdx.x == 0 && threadIdx.x == 0) { g_bar = 0; g_sel[0] = 0; }
    __shared__ float tile[32][33];
    const int b  = blockIdx.x >> 8;
    const int t  = blockIdx.x & 255;
    const int ct = t >> 5;            // c-tile 0..7
    const int ht = t & 31;            // hw-tile 0..31
    const int tx = threadIdx.x & 31;
    const int ty = threadIdx.x >> 5;  // 0..7

    const float* src = in + ((size_t)b * C_DIM + ct * 32) * HW + ht * 32;
    #pragma unroll
    for (int r = 0; r < 4; ++r)
        tile[ty + r * 8][tx] = src[(size_t)(ty + r * 8) * HW + tx];
    __syncthreads();

    float* dst = g_feat + ((size_t)b * HW + ht * 32) * C_DIM + ct * 32;
    #pragma unroll
    for (int r = 0; r < 4; ++r)
        dst[(size_t)(ty + r * 8) * C_DIM + tx] = tile[tx][ty + r * 8];
}

// ---------------------------------------------------------------------------
// Init B: int8 quantization. One warp per point; lane l owns cols 8l..8l+7.
// ---------------------------------------------------------------------------
__global__ void k_quant() {
    const int p    = blockIdx.x * 8 + (threadIdx.x >> 5);
    const int lane = threadIdx.x & 31;
    const float4* row = reinterpret_cast<const float4*>(g_feat + (size_t)p * C_DIM);
    float4 va = row[2 * lane];
    float4 vb = row[2 * lane + 1];

    float m = fmaxf(fmaxf(fmaxf(fabsf(va.x), fabsf(va.y)), fmaxf(fabsf(va.z), fabsf(va.w))),
                    fmaxf(fmaxf(fabsf(vb.x), fabsf(vb.y)), fmaxf(fabsf(vb.z), fabsf(vb.w))));
    #pragma unroll
    for (int off = 16; off; off >>= 1)
        m = fmaxf(m, __shfl_xor_sync(0xffffffffu, m, off));
    m = fmaxf(m, 1e-30f);
    const float scale = m * (1.f / 127.f);
    const float inv   = 127.f / m;

    int i0 = (int)rintf(va.x * inv), i1 = (int)rintf(va.y * inv);
    int i2 = (int)rintf(va.z * inv), i3 = (int)rintf(va.w * inv);
    int i4 = (int)rintf(vb.x * inv), i5 = (int)rintf(vb.y * inv);
    int i6 = (int)rintf(vb.z * inv), i7 = (int)rintf(vb.w * inv);

    unsigned w0 = (unsigned)(i0 & 0xff) | ((unsigned)(i1 & 0xff) << 8)
                | ((unsigned)(i2 & 0xff) << 16) | ((unsigned)(i3 & 0xff) << 24);
    unsigned w1 = (unsigned)(i4 & 0xff) | ((unsigned)(i5 & 0xff) << 8)
                | ((unsigned)(i6 & 0xff) << 16) | ((unsigned)(i7 & 0xff) << 24);
    g_q8[(size_t)p * 32 + lane] = make_uint2(w0, w1);

    int s2 = __dp4a((int)w0, (int)w0, __dp4a((int)w1, (int)w1, 0));
    float e, se2 = 0.f;
    e = va.x - scale * (float)i0; se2 = fmaf(e, e, se2);
    e = va.y - scale * (float)i1; se2 = fmaf(e, e, se2);
    e = va.z - scale * (float)i2; se2 = fmaf(e, e, se2);
    e = va.w - scale * (float)i3; se2 = fmaf(e, e, se2);
    e = vb.x - scale * (float)i4; se2 = fmaf(e, e, se2);
    e = vb.y - scale * (float)i5; se2 = fmaf(e, e, se2);
    e = vb.z - scale * (float)i6; se2 = fmaf(e, e, se2);
    e = vb.w - scale * (float)i7; se2 = fmaf(e, e, se2);
    #pragma unroll
    for (int off = 16; off; off >>= 1) {
        s2  += __shfl_xor_sync(0xffffffffu, s2, off);
        se2 += __shfl_xor_sync(0xffffffffu, se2, off);
    }
    if (lane == 0) {
        g_sv[p]   = scale;
        g_nvh2[p] = scale * scale * (float)s2;
        g_env[p]  = sqrtf(se2 * 1.0001f + 1e-12f) * 1.0001f;
    }
}

// ---------------------------------------------------------------------------
// Persistent FPS with certified int8 screen.
// Exact path (on screen failure) is the verified bit-exact XLA warp reduce.
// ---------------------------------------------------------------------------
__global__ void __launch_bounds__(NTHR, 1) k_fps() {
    __shared__ __align__(16) float sq[C_DIM];   // query vector (exact fp32)
    __shared__ int s_q8[64];                    // quantized query (packed)
    __shared__ float s_sq, s_nqh2, s_enq;
    __shared__ unsigned long long swarp[NTHR / 32];
    __shared__ int s_qidx;

    const int tid  = threadIdx.x;
    const int lane = tid & 31;
    const int wid  = tid >> 5;                  // 0..23
    const int n0   = blockIdx.x * NTHR + wid * 32;
    const uint2* __restrict__ qbase = g_q8   + (size_t)n0 * 32;
    const float* __restrict__ fbase = g_feat + (size_t)n0 * C_DIM;
    const int mypoint = n0 + lane;

    float mind = CUDART_INF_F;

    // hoisted per-point screen constants
    const float mysv   = g_sv[mypoint];
    const float mynvh2 = g_nvh2[mypoint];
    const float myenv  = g_env[mypoint];

    if (tid < C_DIM) sq[tid] = g_feat[tid];     // initial query: row 0
    __syncthreads();

    for (int it = 0; it < NITER; ++it) {
        // ---- (A) quantize current query (warp 0), broadcast via smem ----
        if (wid == 0) {
            const float4* qr = reinterpret_cast<const float4*>(sq);
            float4 va = qr[2 * lane];
            float4 vb = qr[2 * lane + 1];
            float m = fmaxf(fmaxf(fmaxf(fabsf(va.x), fabsf(va.y)), fmaxf(fabsf(va.z), fabsf(va.w))),
                            fmaxf(fmaxf(fabsf(vb.x), fabsf(vb.y)), fmaxf(fabsf(vb.z), fabsf(vb.w))));
            #pragma unroll
            for (int off = 16; off; off >>= 1)
                m = fmaxf(m, __shfl_xor_sync(0xffffffffu, m, off));
            m = fmaxf(m, 1e-30f);
            const float scale = m * (1.f / 127.f);
            const float inv   = 127.f / m;
            int i0 = (int)rintf(va.x * inv), i1 = (int)rintf(va.y * inv);
            int i2 = (int)rintf(va.z * inv), i3 = (int)rintf(va.w * inv);
            int i4 = (int)rintf(vb.x * inv), i5 = (int)rintf(vb.y * inv);
            int i6 = (int)rintf(vb.z * inv), i7 = (int)rintf(vb.w * inv);
            unsigned w0 = (unsigned)(i0 & 0xff) | ((unsigned)(i1 & 0xff) << 8)
                        | ((unsigned)(i2 & 0xff) << 16) | ((unsigned)(i3 & 0xff) << 24);
            unsigned w1 = (unsigned)(i4 & 0xff) | ((unsigned)(i5 & 0xff) << 8)
                        | ((unsigned)(i6 & 0xff) << 16) | ((unsigned)(i7 & 0xff) << 24);
            s_q8[2 * lane]     = (int)w0;
            s_q8[2 * lane + 1] = (int)w1;
            int s2 = __dp4a((int)w0, (int)w0, __dp4a((int)w1, (int)w1, 0));
            float e, se2 = 0.f;
            e = va.x - scale * (float)i0; se2 = fmaf(e, e, se2);
            e = va.y - scale * (float)i1; se2 = fmaf(e, e, se2);
            e = va.z - scale * (float)i2; se2 = fmaf(e, e, se2);
            e = va.w - scale * (float)i3; se2 = fmaf(e, e, se2);
            e = vb.x - scale * (float)i4; se2 = fmaf(e, e, se2);
            e = vb.y - scale * (float)i5; se2 = fmaf(e, e, se2);
            e = vb.z - scale * (float)i6; se2 = fmaf(e, e, se2);
            e = vb.w - scale * (float)i7; se2 = fmaf(e, e, se2);
            #pragma unroll
            for (int off = 16; off; off >>= 1) {
                s2  += __shfl_xor_sync(0xffffffffu, s2, off);
                se2 += __shfl_xor_sync(0xffffffffu, se2, off);
            }
            if (lane == 0) {
                s_sq   = scale;
                s_nqh2 = scale * scale * (float)s2;
                s_enq  = sqrtf(se2 * 1.0001f + 1e-12f) * 1.0001f;
            }
        }
        __syncthreads();

        const int q0 = s_q8[2 * lane];
        const int q1 = s_q8[2 * lane + 1];
        const float ss    = mysv * s_sq;
        const float cnqh2 = s_nqh2;
        const float cenq  = s_enq;

        // ---- (B) int8 screen: exact integer dots for the warp's 32 points.
        // Stage 1 fused into the loads (merge point i with i+16 via lane bit 16),
        // then butterfly halving on 16 -> lane l ends with dot of point n0+l.
        int p16[16];
        #pragma unroll
        for (int i = 0; i < 16; ++i) {
            uint2 a = qbase[(size_t)i * 32 + lane];
            uint2 b = qbase[(size_t)(i + 16) * 32 + lane];
            int da = __dp4a((int)a.y, q1, __dp4a((int)a.x, q0, 0));
            int db = __dp4a((int)b.y, q1, __dp4a((int)b.x, q0, 0));
            int send = (lane & 16) ? da : db;
            int keep = (lane & 16) ? db : da;
            p16[i] = keep + __shfl_xor_sync(0xffffffffu, send, 16);
        }
        #pragma unroll
        for (int off = 8; off >= 1; off >>= 1) {
            #pragma unroll
            for (int k = 0; k < 8; ++k) {
                if (k < off) {
                    int send = (lane & off) ? p16[k] : p16[k + off];
                    int keep = (lane & off) ? p16[k + off] : p16[k];
                    p16[k] = keep + __shfl_xor_sync(0xffffffffu, send, off);
                }
            }
        }
        // certified lower bound: d >= ||vhat-qhat|| - ||ev|| - ||eq|| - pad
        float t  = mynvh2 + cnqh2 - 2.f * ss * (float)p16[0];
        float lb = sqrtf(fmaxf(t, 0.f)) * (1.f - 1e-6f) - myenv - cenq - 0.01f;
        bool need = !(lb >= mind);                 // NaN/inf-safe

        // ---- exact recheck (bit-exact XLA reduce) for flagged points ----
        unsigned mask = __ballot_sync(0xffffffffu, need);
        while (mask) {
            const int i = __ffs(mask) - 1;
            mask &= mask - 1;
            const float* row = fbase + (size_t)i * C_DIM;
            float a = 0.f;
            #pragma unroll
            for (int j = 0; j < 8; ++j) {
                float v = row[j * 32 + lane];
                float d = __fsub_rn(v, sq[j * 32 + lane]);
                a = __fadd_rn(a, __fmul_rn(d, d));     // no contraction
            }
            #pragma unroll
            for (int off = 16; off; off >>= 1)
                a = __fadd_rn(a, __shfl_down_sync(0xffffffffu, a, off));
            float s = __shfl_sync(0xffffffffu, a, 0);
            if (lane == i) mind = fminf(mind, __fsqrt_rn(s));
        }

        // ---- argmax, first-index-wins: key = bits(min_d)<<32 | ~idx ----
        unsigned long long best =
            ((unsigned long long)__float_as_uint(mind) << 32) | (unsigned)~mypoint;
        #pragma unroll
        for (int off = 16; off; off >>= 1) {
            unsigned long long o = __shfl_xor_sync(0xffffffffu, best, off);
            if (o > best) best = o;
        }
        if (lane == 0) swarp[wid] = best;
        __syncthreads();

        if (wid == 0) {
            unsigned long long b = (lane < NTHR / 32) ? swarp[lane] : 0ULL;
            #pragma unroll
            for (int off = 16; off; off >>= 1) {
                unsigned long long o = __shfl_xor_sync(0xffffffffu, b, off);
                if (o > b) b = o;
            }
            if (lane == 0) {
                *(volatile unsigned long long*)&g_bmax[it & 1][blockIdx.x] = b;
                __threadfence();                           // release
                atomicAdd((unsigned*)&g_bar, 1u);
                const unsigned target = (unsigned)NBLK * (unsigned)(it + 1);
                while (g_bar < target) { }                 // grid barrier spin
                __threadfence();                           // acquire
            }
        }
        __syncthreads();

        // ---- every block redundantly reduces the 128 block maxima ----
        if (wid == 0) {
            unsigned long long b = 0;
            #pragma unroll
            for (int j = 0; j < NBLK / 32; ++j) {
                unsigned long long o =
                    *(volatile unsigned long long*)&g_bmax[it & 1][j * 32 + lane];
                if (o > b) b = o;
            }
            #pragma unroll
            for (int off = 16; off; off >>= 1) {
                unsigned long long o = __shfl_xor_sync(0xffffffffu, b, off);
                if (o > b) b = o;
            }
            if (lane == 0) {
                const int q = (int)~(unsigned)b;
                s_qidx = q;
                if (blockIdx.x == 0) g_sel[it + 1] = q;
            }
        }
        __syncthreads();

        // ---- (C) load next query row (contiguous fp32) into shared ----
        const int q = s_qidx;
        if (tid < C_DIM) sq[tid] = g_feat[(size_t)q * C_DIM + tid];
        __syncthreads();
    }
}

// ---------------------------------------------------------------------------
// Gather: out = [sampled feats (491*256) | sampled weights (491) | indices (491)]
// ---------------------------------------------------------------------------
__global__ void k_gather(const float* __restrict__ w, float* __restrict__ out) {
    const int s = blockIdx.x;           // 0..490
    const int idx = g_sel[s];
    out[s * C_DIM + threadIdx.x] = g_feat[(size_t)idx * C_DIM + threadIdx.x];
    if (threadIdx.x == 0) {
        out[NSAMP * C_DIM + s]         = w[idx];
        out[NSAMP * C_DIM + NSAMP + s] = (float)idx;
    }
}

// ---------------------------------------------------------------------------
extern "C" void kernel_launch(void* const* d_in, const int* in_sizes, int n_in,
                              void* d_out, int out_size) {
    const float* features = (const float*)d_in[0];   // [96,256,32,32] f32
    const float* weights  = (const float*)d_in[1];   // [98304] f32
    (void)in_sizes; (void)n_in; (void)out_size;      // num_samples fixed at 491

    k_init<<<(96 * 256), 256>>>(features);
    k_quant<<<N_PTS / 8, 256>>>();
    k_fps<<<NBLK, NTHR>>>();
    k_gather<<<NSAMP, C_DIM>>>(weights, (float*)d_out);
}